// round 16
// baseline (speedup 1.0000x reference)
#include <cuda_runtime.h>
#include <cuda_fp16.h>
#include <cstdint>
#include <math.h>

#define NPTS   400000
#define KOFF   27
#define TILE_M 128
#define NTILES (NPTS / TILE_M)    // 3125 exact
#define CPAD   64                 // padded channel dim -> 128B fp16 rows
#define NOUT   38
#define NPADB  40                 // MMA N (5 x n8 tiles)

// ---------------- global scratch (static zero-init; no allocation) ----------------
// Features / hidden: single fp16 (rounding 2^-12 ~ 1.4e-4 aggregate, inside 1e-3 budget)
// Weights: fp16 hi+lo split (2^-22, negligible)
__device__ __half g_f [(size_t)(NPTS + 1) * CPAD];
__device__ __half g_h [(size_t)(NPTS + 1) * CPAD];   // cols >= NOUT stay zero forever
__device__ __half g_w1hi[KOFF * NPADB * CPAD];
__device__ __half g_w1lo[KOFF * NPADB * CPAD];
__device__ __half g_w2hi[KOFF * NPADB * CPAD];
__device__ __half g_w2lo[KOFF * NPADB * CPAD];

// ---------------- helpers ----------------
__device__ __forceinline__ uint32_t smem_u32(const void* p) {
    uint32_t a;
    asm("{ .reg .u64 t; cvta.to.shared.u64 t, %1; cvt.u32.u64 %0, t; }" : "=r"(a) : "l"(p));
    return a;
}
#define SWZ(o) (((uint32_t)(o)) ^ ((((uint32_t)(o)) >> 3) & 0x70))

// L1-caching async copy (preserves cross-k neighbor-row reuse in L1)
__device__ __forceinline__ void cp16ca(uint32_t dst, const void* src) {
    asm volatile("cp.async.ca.shared.global [%0], [%1], 16;" :: "r"(dst), "l"(src) : "memory");
}
__device__ __forceinline__ void cp_commit() {
    asm volatile("cp.async.commit_group;" ::: "memory");
}
__device__ __forceinline__ void cp_wait1() {
    asm volatile("cp.async.wait_group 1;" ::: "memory");
}
__device__ __forceinline__ void cp_wait0() {
    asm volatile("cp.async.wait_group 0;" ::: "memory");
}

__device__ __forceinline__ void ldsm_x4(uint32_t* r, uint32_t addr) {
    asm volatile("ldmatrix.sync.aligned.m8n8.x4.shared.b16 {%0,%1,%2,%3}, [%4];"
                 : "=r"(r[0]), "=r"(r[1]), "=r"(r[2]), "=r"(r[3]) : "r"(addr));
}
__device__ __forceinline__ void ldsm_x2(uint32_t* r, uint32_t addr) {
    asm volatile("ldmatrix.sync.aligned.m8n8.x2.shared.b16 {%0,%1}, [%2];"
                 : "=r"(r[0]), "=r"(r[1]) : "r"(addr));
}
__device__ __forceinline__ void mma_f16(float* d, const uint32_t* a, uint32_t b0, uint32_t b1) {
    asm volatile("mma.sync.aligned.m16n8k16.row.col.f32.f16.f16.f32 "
                 "{%0,%1,%2,%3}, {%4,%5,%6,%7}, {%8,%9}, {%0,%1,%2,%3};"
                 : "+f"(d[0]), "+f"(d[1]), "+f"(d[2]), "+f"(d[3])
                 : "r"(a[0]), "r"(a[1]), "r"(a[2]), "r"(a[3]), "r"(b0), "r"(b1));
}

// ---------------- smem layout (dynamic, 1024B-aligned base) ----------------
// A stage s in {0,1}: 128 rows x 128B at s*16384 ; B at 32768 (hi 40 rows + lo 40 rows)
#define ASTAGE   16384u
#define B_OFF    32768u
#define BLO_REL  5120u
#define SMEM_DYN 44032u   // 43008 + alignment slack; 4 CTAs/SM

// ---------------- prep kernels ----------------
__global__ void prep_w(const float* __restrict__ W1, const float* __restrict__ W2) {
    int idx = blockIdx.x * 256 + threadIdx.x;
    if (idx >= KOFF * NPADB * CPAD) return;
    int j = idx & (CPAD - 1);
    int n = (idx / CPAD) % NPADB;
    int k = idx / (CPAD * NPADB);
    float w1 = (n < NOUT) ? W1[(k * 64 + j) * NOUT + n] : 0.0f;
    float w2 = (n < NOUT && j < NOUT) ? W2[(k * NOUT + j) * NOUT + n] : 0.0f;
    __half h1 = __float2half(w1);
    g_w1hi[idx] = h1;
    g_w1lo[idx] = __float2half(w1 - __half2float(h1));
    __half h2 = __float2half(w2);
    g_w2hi[idx] = h2;
    g_w2lo[idx] = __float2half(w2 - __half2float(h2));
}

__global__ void prep_f(const float* __restrict__ feat) {
    size_t idx = (size_t)blockIdx.x * 256 + threadIdx.x;
    if (idx >= (size_t)(NPTS + 1) * CPAD) return;
    size_t i = idx >> 6;
    g_f[idx] = __float2half((i < NPTS) ? feat[idx] : 0.0f);
    // g_h padding (row NPTS, cols>=NOUT) is static-zero and never written: safe.
}

// ---------------- main conv kernel: pipelined gather + 2-pass (Bhi,Blo) fp16 HMMA ----------------
template <int NKS, bool LAYER2>
__global__ void __launch_bounds__(128, 4) conv_mma(const int* __restrict__ nbr,
                                                   float* __restrict__ out) {
    extern __shared__ char smraw[];
    const uint32_t smu = (smem_u32(smraw) + 1023u) & ~1023u;
    char* smb = smraw + (smu - smem_u32(smraw));
    const int t = threadIdx.x;
    const int lane = t & 31;
    const int wid = t >> 5;               // 0..3, warp owns rows [wid*32, wid*32+32)
    const int i0 = blockIdx.x * TILE_M;

    const __half* __restrict__ src = LAYER2 ? g_h : g_f;
    const __half* __restrict__ whi = LAYER2 ? g_w2hi : g_w1hi;
    const __half* __restrict__ wlo = LAYER2 ? g_w2lo : g_w1lo;

    float acc[2][5][4];
#pragma unroll
    for (int mt = 0; mt < 2; ++mt)
#pragma unroll
        for (int nt = 0; nt < 5; ++nt)
#pragma unroll
            for (int q = 0; q < 4; ++q) acc[mt][nt][q] = 0.0f;

    // per-thread ldmatrix address components
    const int a_r = (lane & 7) + ((lane >> 3) & 1) * 8;
    const int a_half = (lane >> 4) << 4;
    const int b_r = lane & 7;
    const int b_sub = (lane >> 3) & 3;

    // A gather for offset k into stage buffer (8 cp.async.ca / thread, one group)
    auto issue_A = [&](int k, uint32_t abase) {
#pragma unroll
        for (int i = 0; i < 8; ++i) {
            int q = t + 128 * i;       // 0..1023
            int row = q >> 3, c = q & 7;
            int nb = __ldg(nbr + (size_t)k * NPTS + i0 + row);
            cp16ca(abase + SWZ(row * 128 + c * 16), src + (size_t)nb * CPAD + c * 8);
        }
        cp_commit();
    };

    // ---- prologue ----
    issue_A(0, smu);

    for (int k = 0; k < KOFF; ++k) {
        const uint32_t abase = smu + (uint32_t)(k & 1) * ASTAGE;
        if (k + 1 < KOFF)
            issue_A(k + 1, smu + (uint32_t)((k + 1) & 1) * ASTAGE);

        // stage B(k): hi rows 0..39, lo rows 0..39 at BLO_REL (weights L1/L2-hot)
        {
            const __half* wkh = whi + k * (NPADB * CPAD);
            const __half* wkl = wlo + k * (NPADB * CPAD);
#pragma unroll
            for (int i = 0; i < 3; ++i) {
                int q = t + 128 * i;
                if (q < NPADB * 8) {
                    int row = q >> 3, c = q & 7;
                    uint32_t off = SWZ(row * 128 + c * 16);
                    *(uint4*)(smb + B_OFF + off) = *(const uint4*)(wkh + row * CPAD + c * 8);
                    *(uint4*)(smb + B_OFF + BLO_REL + off) = *(const uint4*)(wkl + row * CPAD + c * 8);
                }
            }
        }

        if (k + 1 < KOFF) cp_wait1();  // A(k) landed; A(k+1) still in flight
        else              cp_wait0();
        __syncthreads();               // A(k)+B(k) visible to all warps

        // ---- load A fragments (single fp16, both m-subtiles) once ----
        uint32_t a[2][NKS][4];
#pragma unroll
        for (int mt = 0; mt < 2; ++mt) {
            const int arow = wid * 32 + mt * 16 + a_r;
#pragma unroll
            for (int ks = 0; ks < NKS; ++ks)
                ldsm_x4(a[mt][ks], abase + SWZ(arow * 128 + ks * 32 + a_half));
        }

        // ---- single B sweep: each (Bhi,Blo) frag loaded once, 2-pass accumulate ----
#pragma unroll
        for (int nt = 0; nt < 5; ++nt) {
            const int brow = nt * 8 + b_r;
#pragma unroll
            for (int ks2 = 0; ks2 < NKS / 2; ++ks2) {
                uint32_t bh[4], bl[4];
                ldsm_x4(bh, smu + B_OFF + SWZ(brow * 128 + ks2 * 64 + b_sub * 16));
                ldsm_x4(bl, smu + B_OFF + BLO_REL + SWZ(brow * 128 + ks2 * 64 + b_sub * 16));
                mma_f16(acc[0][nt], a[0][2 * ks2],     bh[0], bh[1]);
                mma_f16(acc[1][nt], a[1][2 * ks2],     bh[0], bh[1]);
                mma_f16(acc[0][nt], a[0][2 * ks2 + 1], bh[2], bh[3]);
                mma_f16(acc[1][nt], a[1][2 * ks2 + 1], bh[2], bh[3]);
                mma_f16(acc[0][nt], a[0][2 * ks2],     bl[0], bl[1]);
                mma_f16(acc[1][nt], a[1][2 * ks2],     bl[0], bl[1]);
                mma_f16(acc[0][nt], a[0][2 * ks2 + 1], bl[2], bl[3]);
                mma_f16(acc[1][nt], a[1][2 * ks2 + 1], bl[2], bl[3]);
            }
            if (NKS & 1) {
                uint32_t bh[2], bl[2];
                ldsm_x2(bh, smu + B_OFF + SWZ(brow * 128 + (NKS - 1) * 32 + (b_sub & 1) * 16));
                ldsm_x2(bl, smu + B_OFF + BLO_REL + SWZ(brow * 128 + (NKS - 1) * 32 + (b_sub & 1) * 16));
                mma_f16(acc[0][nt], a[0][NKS - 1], bh[0], bh[1]);
                mma_f16(acc[1][nt], a[1][NKS - 1], bh[0], bh[1]);
                mma_f16(acc[0][nt], a[0][NKS - 1], bl[0], bl[1]);
                mma_f16(acc[1][nt], a[1][NKS - 1], bl[0], bl[1]);
            }
        }
        __syncthreads();   // compute(k) done: B smem / A stage may be overwritten
    }

    // ---- epilogue ----
#pragma unroll
    for (int mt = 0; mt < 2; ++mt) {
        const int r1 = i0 + wid * 32 + mt * 16 + (lane >> 2);
#pragma unroll
        for (int half = 0; half < 2; ++half) {
            const int row = r1 + half * 8;
#pragma unroll
            for (int nt = 0; nt < 5; ++nt) {
                const int c = nt * 8 + (lane & 3) * 2;
                float v0 = acc[mt][nt][half * 2 + 0];
                float v1 = acc[mt][nt][half * 2 + 1];
                if (LAYER2) {
                    if (c < NOUT) {
                        float* o = out + (size_t)row * NOUT + c;
                        o[0] = v0;
                        if (c + 1 < NOUT) o[1] = v1;
                    }
                } else {
                    if (c < NOUT) {   // NOUT=38 even: pairs (36,37) complete
                        v0 = 0.5f * v0 * (1.0f + erff(v0 * 0.7071067811865475f));
                        v1 = 0.5f * v1 * (1.0f + erff(v1 * 0.7071067811865475f));
                        __half2 hp;
                        hp.x = __float2half(v0);
                        hp.y = __float2half(v1);
                        *(__half2*)(g_h + (size_t)row * CPAD + c) = hp;
                    }
                }
            }
        }
    }
}

// ---------------- launch ----------------
extern "C" void kernel_launch(void* const* d_in, const int* in_sizes, int n_in,
                              void* d_out, int out_size) {
    const float* feat = (const float*)d_in[0];  // [N, 64] f32
    const int* nbr    = (const int*)d_in[1];    // [27, N] i32
    const float* W1   = (const float*)d_in[2];  // [27, 64, 38] f32
    const float* W2   = (const float*)d_in[3];  // [27, 38, 38] f32
    float* out        = (float*)d_out;          // [N, 38] f32

    cudaFuncSetAttribute(conv_mma<4, false>, cudaFuncAttributeMaxDynamicSharedMemorySize, SMEM_DYN);
    cudaFuncSetAttribute(conv_mma<3, true >, cudaFuncAttributeMaxDynamicSharedMemorySize, SMEM_DYN);

    prep_w<<<(KOFF * NPADB * CPAD + 255) / 256, 256>>>(W1, W2);
    {
        size_t tot = (size_t)(NPTS + 1) * CPAD;
        prep_f<<<(unsigned)((tot + 255) / 256), 256>>>(feat);
    }
    conv_mma<4, false><<<NTILES, 128, SMEM_DYN>>>(nbr, nullptr);  // layer1 -> g_h (fp16)
    conv_mma<3, true ><<<NTILES, 128, SMEM_DYN>>>(nbr, out);      // layer2
}

// round 17
// speedup vs baseline: 1.4453x; 1.4453x over previous
#include <cuda_runtime.h>
#include <cuda_fp16.h>
#include <cstdint>
#include <math.h>

#define NPTS   400000
#define KOFF   27
#define TILE_M 128
#define NTILES (NPTS / TILE_M)    // 3125 exact
#define CPAD   64                 // padded channel dim -> 128B fp16 rows
#define NOUT   38
#define NPADB  40                 // MMA N (5 x n8 tiles)

// ---------------- global scratch (static zero-init; no allocation) ----------------
// Features / hidden: single fp16 (rounding 2^-12 ~ 1.4e-4 aggregate, inside 1e-3 budget)
// Weights: fp16 hi+lo split (2^-22, negligible)
__device__ __half g_f [(size_t)(NPTS + 1) * CPAD];
__device__ __half g_h [(size_t)(NPTS + 1) * CPAD];   // cols >= NOUT stay zero forever
__device__ __half g_w1hi[KOFF * NPADB * CPAD];
__device__ __half g_w1lo[KOFF * NPADB * CPAD];
__device__ __half g_w2hi[KOFF * NPADB * CPAD];
__device__ __half g_w2lo[KOFF * NPADB * CPAD];

// ---------------- helpers ----------------
__device__ __forceinline__ uint32_t smem_u32(const void* p) {
    uint32_t a;
    asm("{ .reg .u64 t; cvta.to.shared.u64 t, %1; cvt.u32.u64 %0, t; }" : "=r"(a) : "l"(p));
    return a;
}
#define SWZ(o) (((uint32_t)(o)) ^ ((((uint32_t)(o)) >> 3) & 0x70))

// L1-caching async copy (preserves cross-k neighbor-row reuse in L1)
__device__ __forceinline__ void cp16ca(uint32_t dst, const void* src) {
    asm volatile("cp.async.ca.shared.global [%0], [%1], 16;" :: "r"(dst), "l"(src) : "memory");
}
__device__ __forceinline__ void cp_commit() {
    asm volatile("cp.async.commit_group;" ::: "memory");
}
__device__ __forceinline__ void cp_wait1() {
    asm volatile("cp.async.wait_group 1;" ::: "memory");
}
__device__ __forceinline__ void cp_wait0() {
    asm volatile("cp.async.wait_group 0;" ::: "memory");
}

__device__ __forceinline__ void ldsm_x4(uint32_t* r, uint32_t addr) {
    asm volatile("ldmatrix.sync.aligned.m8n8.x4.shared.b16 {%0,%1,%2,%3}, [%4];"
                 : "=r"(r[0]), "=r"(r[1]), "=r"(r[2]), "=r"(r[3]) : "r"(addr));
}
__device__ __forceinline__ void mma_f16(float* d, const uint32_t* a, uint32_t b0, uint32_t b1) {
    asm volatile("mma.sync.aligned.m16n8k16.row.col.f32.f16.f16.f32 "
                 "{%0,%1,%2,%3}, {%4,%5,%6,%7}, {%8,%9}, {%0,%1,%2,%3};"
                 : "+f"(d[0]), "+f"(d[1]), "+f"(d[2]), "+f"(d[3])
                 : "r"(a[0]), "r"(a[1]), "r"(a[2]), "r"(a[3]), "r"(b0), "r"(b1));
}

// ---------------- smem layout (dynamic, 1024B-aligned base) ----------------
// A stage s in {0,1}: 128 rows x 128B at s*16384 ; B at 32768 (hi 40 rows + lo 40 rows)
#define ASTAGE   16384u
#define B_OFF    32768u
#define BLO_REL  5120u
#define SMEM_DYN 44032u   // 43008 + alignment slack

// ---------------- prep kernels ----------------
__global__ void prep_w(const float* __restrict__ W1, const float* __restrict__ W2) {
    int idx = blockIdx.x * 256 + threadIdx.x;
    if (idx >= KOFF * NPADB * CPAD) return;
    int j = idx & (CPAD - 1);
    int n = (idx / CPAD) % NPADB;
    int k = idx / (CPAD * NPADB);
    float w1 = (n < NOUT) ? W1[(k * 64 + j) * NOUT + n] : 0.0f;
    float w2 = (n < NOUT && j < NOUT) ? W2[(k * NOUT + j) * NOUT + n] : 0.0f;
    __half h1 = __float2half(w1);
    g_w1hi[idx] = h1;
    g_w1lo[idx] = __float2half(w1 - __half2float(h1));
    __half h2 = __float2half(w2);
    g_w2hi[idx] = h2;
    g_w2lo[idx] = __float2half(w2 - __half2float(h2));
}

__global__ void prep_f(const float* __restrict__ feat) {
    size_t idx = (size_t)blockIdx.x * 256 + threadIdx.x;
    if (idx >= (size_t)(NPTS + 1) * CPAD) return;
    size_t i = idx >> 6;
    g_f[idx] = __float2half((i < NPTS) ? feat[idx] : 0.0f);
}

// ---------------- main conv kernel: pipelined gather + 2-pass (Bhi,Blo) fp16 HMMA ----------------
// 3 CTAs/SM: reg budget ~170 -> no spills (R16's (128,4) cap at 128 regs spilled and regressed)
template <int NKS, bool LAYER2>
__global__ void __launch_bounds__(128, 3) conv_mma(const int* __restrict__ nbr,
                                                   float* __restrict__ out) {
    extern __shared__ char smraw[];
    const uint32_t smu = (smem_u32(smraw) + 1023u) & ~1023u;
    char* smb = smraw + (smu - smem_u32(smraw));
    const int t = threadIdx.x;
    const int lane = t & 31;
    const int wid = t >> 5;               // 0..3, warp owns rows [wid*32, wid*32+32)
    const int i0 = blockIdx.x * TILE_M;

    const __half* __restrict__ src = LAYER2 ? g_h : g_f;
    const __half* __restrict__ whi = LAYER2 ? g_w2hi : g_w1hi;
    const __half* __restrict__ wlo = LAYER2 ? g_w2lo : g_w1lo;

    float acc[2][5][4];
#pragma unroll
    for (int mt = 0; mt < 2; ++mt)
#pragma unroll
        for (int nt = 0; nt < 5; ++nt)
#pragma unroll
            for (int q = 0; q < 4; ++q) acc[mt][nt][q] = 0.0f;

    // per-thread ldmatrix address components
    const int a_r = (lane & 7) + ((lane >> 3) & 1) * 8;
    const int a_half = (lane >> 4) << 4;
    const int b_r = lane & 7;
    const int b_sub = (lane >> 3) & 3;

    // A gather for offset k into stage buffer (8 cp.async.ca / thread, one group)
    auto issue_A = [&](int k, uint32_t abase) {
#pragma unroll
        for (int i = 0; i < 8; ++i) {
            int q = t + 128 * i;       // 0..1023
            int row = q >> 3, c = q & 7;
            int nb = __ldg(nbr + (size_t)k * NPTS + i0 + row);
            cp16ca(abase + SWZ(row * 128 + c * 16), src + (size_t)nb * CPAD + c * 8);
        }
        cp_commit();
    };

    // ---- prologue ----
    issue_A(0, smu);

    for (int k = 0; k < KOFF; ++k) {
        const uint32_t abase = smu + (uint32_t)(k & 1) * ASTAGE;
        if (k + 1 < KOFF)
            issue_A(k + 1, smu + (uint32_t)((k + 1) & 1) * ASTAGE);

        // stage B(k): hi rows 0..39 at B_OFF, lo rows at B_OFF+BLO_REL (weights L1/L2-hot)
        {
            const __half* wkh = whi + k * (NPADB * CPAD);
            const __half* wkl = wlo + k * (NPADB * CPAD);
#pragma unroll
            for (int i = 0; i < 3; ++i) {
                int q = t + 128 * i;
                if (q < NPADB * 8) {
                    int row = q >> 3, c = q & 7;
                    uint32_t off = SWZ(row * 128 + c * 16);
                    *(uint4*)(smb + B_OFF + off) = *(const uint4*)(wkh + row * CPAD + c * 8);
                    *(uint4*)(smb + B_OFF + BLO_REL + off) = *(const uint4*)(wkl + row * CPAD + c * 8);
                }
            }
        }

        if (k + 1 < KOFF) cp_wait1();  // A(k) landed; A(k+1) still in flight
        else              cp_wait0();
        __syncthreads();               // A(k)+B(k) visible to all warps

        // ---- load A fragments (single fp16, both m-subtiles) once ----
        uint32_t a[2][NKS][4];
#pragma unroll
        for (int mt = 0; mt < 2; ++mt) {
            const int arow = wid * 32 + mt * 16 + a_r;
#pragma unroll
            for (int ks = 0; ks < NKS; ++ks)
                ldsm_x4(a[mt][ks], abase + SWZ(arow * 128 + ks * 32 + a_half));
        }

        // ---- single B sweep: each (Bhi,Blo) frag loaded once, 2-pass accumulate ----
#pragma unroll
        for (int nt = 0; nt < 5; ++nt) {
            const int brow = nt * 8 + b_r;
#pragma unroll
            for (int ks2 = 0; ks2 < NKS / 2; ++ks2) {
                uint32_t bh[4], bl[4];
                ldsm_x4(bh, smu + B_OFF + SWZ(brow * 128 + ks2 * 64 + b_sub * 16));
                ldsm_x4(bl, smu + B_OFF + BLO_REL + SWZ(brow * 128 + ks2 * 64 + b_sub * 16));
                mma_f16(acc[0][nt], a[0][2 * ks2],     bh[0], bh[1]);
                mma_f16(acc[1][nt], a[1][2 * ks2],     bh[0], bh[1]);
                mma_f16(acc[0][nt], a[0][2 * ks2 + 1], bh[2], bh[3]);
                mma_f16(acc[1][nt], a[1][2 * ks2 + 1], bh[2], bh[3]);
                mma_f16(acc[0][nt], a[0][2 * ks2],     bl[0], bl[1]);
                mma_f16(acc[1][nt], a[1][2 * ks2],     bl[0], bl[1]);
                mma_f16(acc[0][nt], a[0][2 * ks2 + 1], bl[2], bl[3]);
                mma_f16(acc[1][nt], a[1][2 * ks2 + 1], bl[2], bl[3]);
            }
            if (NKS & 1) {
                // folded tail: one x4 ldsm, lane groups 0-1 -> Bhi, groups 2-3 -> Blo
                uint32_t bt[4];
                uint32_t tail = SWZ(brow * 128 + (NKS - 1) * 32 + (b_sub & 1) * 16);
                uint32_t taddr = smu + B_OFF + ((lane >= 16) ? BLO_REL : 0u) + tail;
                ldsm_x4(bt, taddr);
                mma_f16(acc[0][nt], a[0][NKS - 1], bt[0], bt[1]);
                mma_f16(acc[1][nt], a[1][NKS - 1], bt[0], bt[1]);
                mma_f16(acc[0][nt], a[0][NKS - 1], bt[2], bt[3]);
                mma_f16(acc[1][nt], a[1][NKS - 1], bt[2], bt[3]);
            }
        }
        __syncthreads();   // compute(k) done: B smem / A stage may be overwritten
    }

    // ---- epilogue ----
#pragma unroll
    for (int mt = 0; mt < 2; ++mt) {
        const int r1 = i0 + wid * 32 + mt * 16 + (lane >> 2);
#pragma unroll
        for (int half = 0; half < 2; ++half) {
            const int row = r1 + half * 8;
#pragma unroll
            for (int nt = 0; nt < 5; ++nt) {
                const int c = nt * 8 + (lane & 3) * 2;
                float v0 = acc[mt][nt][half * 2 + 0];
                float v1 = acc[mt][nt][half * 2 + 1];
                if (LAYER2) {
                    if (c < NOUT) {
                        float* o = out + (size_t)row * NOUT + c;
                        o[0] = v0;
                        if (c + 1 < NOUT) o[1] = v1;
                    }
                } else {
                    if (c < NOUT) {   // NOUT=38 even: pairs (36,37) complete
                        v0 = 0.5f * v0 * (1.0f + erff(v0 * 0.7071067811865475f));
                        v1 = 0.5f * v1 * (1.0f + erff(v1 * 0.7071067811865475f));
                        __half2 hp;
                        hp.x = __float2half(v0);
                        hp.y = __float2half(v1);
                        *(__half2*)(g_h + (size_t)row * CPAD + c) = hp;
                    }
                }
            }
        }
    }
}

// ---------------- launch ----------------
extern "C" void kernel_launch(void* const* d_in, const int* in_sizes, int n_in,
                              void* d_out, int out_size) {
    const float* feat = (const float*)d_in[0];  // [N, 64] f32
    const int* nbr    = (const int*)d_in[1];    // [27, N] i32
    const float* W1   = (const float*)d_in[2];  // [27, 64, 38] f32
    const float* W2   = (const float*)d_in[3];  // [27, 38, 38] f32
    float* out        = (float*)d_out;          // [N, 38] f32

    cudaFuncSetAttribute(conv_mma<4, false>, cudaFuncAttributeMaxDynamicSharedMemorySize, SMEM_DYN);
    cudaFuncSetAttribute(conv_mma<3, true >, cudaFuncAttributeMaxDynamicSharedMemorySize, SMEM_DYN);

    prep_w<<<(KOFF * NPADB * CPAD + 255) / 256, 256>>>(W1, W2);
    {
        size_t tot = (size_t)(NPTS + 1) * CPAD;
        prep_f<<<(unsigned)((tot + 255) / 256), 256>>>(feat);
    }
    conv_mma<4, false><<<NTILES, 128, SMEM_DYN>>>(nbr, nullptr);  // layer1 -> g_h (fp16)
    conv_mma<3, true ><<<NTILES, 128, SMEM_DYN>>>(nbr, out);      // layer2
}